// round 16
// baseline (speedup 1.0000x reference)
#include <cuda_runtime.h>
#include <cuda_bf16.h>
#include <cuda_fp16.h>
#include <math.h>
#include <stdint.h>

#define B_   1024
#define N_   200
#define E_   256
#define R_   256
#define SIXE 1536

// ---------------- device scratch (static, no allocation) ----------------
__device__ __align__(16) __half g_msgs  [B_ * N_ * E_];   // 105 MB
__device__ __align__(16) __half g_A16   [B_ * N_ * R_];   // 105 MB (fp16 nb_rel)
__device__ __align__(16) __half g_Wh[E_ * R_];            // rel_w fp16 [E,R]
__device__ float  g_attnraw[3 * B_ * N_];
__device__ __align__(16) __half g_feats16[3 * B_ * SIXE];
__device__ __align__(16) __half g_sph[3 * E_ * SIXE];     // sp_w fp16 hi
__device__ __align__(16) __half g_spl[3 * E_ * SIXE];     // sp_w fp16 lo
__device__ float  g_relwT [R_ * E_];
__device__ float  g_attnwT[3 * E_ * E_];
__device__ float  g_csqwT [R_ * E_];
__device__ float  g_qkey  [B_ * E_];
__device__ float  g_qproj [3 * B_ * E_];
__device__ float  g_sq    [B_ * E_];
__device__ float  g_h     [3 * B_ * E_];
__device__ float  g_scales[3 * B_ * E_];
__device__ float4 g_scal4 [B_ * N_];       // (maskf, a0, a1, a2)
__device__ float  g_nvalid[B_];
__device__ int    g_anyvalid[B_];
__device__ int    g_mask_mode;

// ---------------- mask dtype detection ----------------
__global__ void detect_mask_kernel(const unsigned char* __restrict__ raw, int nElems) {
    __shared__ int f1, f23;
    if (threadIdx.x == 0) { f1 = 0; f23 = 0; }
    __syncthreads();
    int lf1 = 0, lf23 = 0;
    for (int i = threadIdx.x; i < nElems; i += blockDim.x) {
        unsigned char v = raw[i];
        if (v) { int m = i & 3; if (m == 1) lf1 = 1; else if (m >= 2) lf23 = 1; }
    }
    if (lf1)  atomicOr(&f1, 1);
    if (lf23) atomicOr(&f23, 1);
    __syncthreads();
    if (threadIdx.x == 0) g_mask_mode = f1 ? 1 : (f23 ? 2 : 0);
}

// ---------------- per-(b,n) scalar precompute ----------------
__global__ void prep_kernel(const void* __restrict__ maskp,
                            const float* __restrict__ delta_t,
                            const float* __restrict__ p_lt1, const float* __restrict__ p_lt2,
                            const float* __restrict__ p_sharp, const float* __restrict__ p_lg) {
    int b = blockIdx.x;
    int n = threadIdx.x;
    __shared__ int s_cnt[256];
    int mode = g_mask_mode;
    float tau1  = expf(*p_lt1);
    float tau2  = expf(*p_lt2) + tau1;
    float sharp = fminf(fmaxf(*p_sharp, 0.1f), 5.0f);
    float gamma = expf(*p_lg);
    int valid = 0;
    if (n < N_) {
        int idx = b * N_ + n;
        if      (mode == 0) valid = ((const int*)maskp)[idx] != 0;
        else if (mode == 1) valid = ((const unsigned char*)maskp)[idx] != 0;
        else                valid = ((const float*)maskp)[idx] != 0.0f;
        float dt    = delta_t[idx];
        float decay = expf(-gamma * fmaxf(dt, 0.0f));
        float wf = 1.0f / (1.0f + expf( sharp * (dt - tau1)));
        float wc = 1.0f / (1.0f + expf(-sharp * (dt - tau2)));
        float wm = fmaxf(1.0f - wf - wc, 0.0f);
        g_scal4[idx] = make_float4(valid ? 1.0f : 0.0f, decay * wf, decay * wm, decay * wc);
    }
    s_cnt[threadIdx.x] = valid;
    __syncthreads();
    for (int off = 128; off > 0; off >>= 1) {
        if (threadIdx.x < off) s_cnt[threadIdx.x] += s_cnt[threadIdx.x + off];
        __syncthreads();
    }
    if (threadIdx.x == 0) {
        g_nvalid[b]   = fmaxf((float)s_cnt[0], 1.0f);
        g_anyvalid[b] = (s_cnt[0] > 0) ? 1 : 0;
    }
}

// ---------------- nb_rel fp32 -> fp16 ----------------
__global__ void aconv_kernel(const float4* __restrict__ src) {
    long i = (long)blockIdx.x * 256 + threadIdx.x;   // 13107200 float4s
    float4 v = src[i];
    __half2 hA(__float2half_rn(v.x), __float2half_rn(v.y));
    __half2 hB(__float2half_rn(v.z), __float2half_rn(v.w));
    *(uint2*)&g_A16[i * 4] = make_uint2(*(uint32_t*)&hA, *(uint32_t*)&hB);
}

// ---------------- W convert + attnraw zero ----------------
__global__ void wconv_kernel(const float* __restrict__ rel_w) {
    int idx = blockIdx.x * 256 + threadIdx.x;        // 16384 float4s
    float4 v = ((const float4*)rel_w)[idx];
    __half2 hA(__float2half_rn(v.x), __float2half_rn(v.y));
    __half2 hB(__float2half_rn(v.z), __float2half_rn(v.w));
    *(uint2*)&g_Wh[idx * 4] = make_uint2(*(uint32_t*)&hA, *(uint32_t*)&hB);
    float4* ar = (float4*)g_attnraw;
    for (int i = idx; i < 153600; i += 16384)
        ar[i] = make_float4(0.f, 0.f, 0.f, 0.f);
}

// ---------------- sp_w split: [3,E,6E] fp32 -> fp16 hi/lo ----------------
__global__ void spsplit_kernel(const float* __restrict__ sp_w) {
    int idx = blockIdx.x * 256 + threadIdx.x;        // 294912 float4s
    float4 v = ((const float4*)sp_w)[idx];
    __half h0 = __float2half_rn(v.x), h1 = __float2half_rn(v.y);
    __half h2 = __float2half_rn(v.z), h3 = __float2half_rn(v.w);
    __half l0 = __float2half_rn(v.x - __half2float(h0));
    __half l1 = __float2half_rn(v.y - __half2float(h1));
    __half l2 = __float2half_rn(v.z - __half2float(h2));
    __half l3 = __float2half_rn(v.w - __half2float(h3));
    __half2 hA(h0, h1), hB(h2, h3), lA(l0, l1), lB(l2, l3);
    *(uint2*)&g_sph[idx * 4] = make_uint2(*(uint32_t*)&hA, *(uint32_t*)&hB);
    *(uint2*)&g_spl[idx * 4] = make_uint2(*(uint32_t*)&lA, *(uint32_t*)&lB);
}

// ---------------- generic transpose ----------------
__global__ void transpose_kernel(const float* __restrict__ in, float* __restrict__ out,
                                 int rows, int cols) {
    long zoff = (long)blockIdx.z * rows * cols;
    in  += zoff;
    out += zoff;
    __shared__ float tile[32][33];
    int c0 = blockIdx.x * 32, r0 = blockIdx.y * 32;
    int c = c0 + threadIdx.x;
    for (int i = threadIdx.y; i < 32; i += 8) {
        int r = r0 + i;
        if (r < rows && c < cols) tile[i][threadIdx.x] = in[(long)r * cols + c];
    }
    __syncthreads();
    int rr = r0 + threadIdx.x;
    for (int i = threadIdx.y; i < 32; i += 8) {
        int cc = c0 + i;
        if (cc < cols && rr < rows) out[(long)cc * rows + rr] = tile[threadIdx.x][i];
    }
}

// ================= common MMA helpers =================
#define CP_ASYNC16(sa, ga) asm volatile("cp.async.cg.shared.global [%0], [%1], 16;\n" :: "r"(sa), "l"(ga))
#define CP_COMMIT()        asm volatile("cp.async.commit_group;\n" ::)
#define CP_WAIT0()         asm volatile("cp.async.wait_group 0;\n" ::)
#define CP_WAIT1()         asm volatile("cp.async.wait_group 1;\n" ::)

__device__ __forceinline__ void ldsm4(unsigned r[4], unsigned addr) {
    asm volatile("ldmatrix.sync.aligned.m8n8.x4.shared.b16 {%0,%1,%2,%3}, [%4];"
                 : "=r"(r[0]), "=r"(r[1]), "=r"(r[2]), "=r"(r[3]) : "r"(addr));
}
__device__ __forceinline__ void mma16816(float c[4], const unsigned a[4], const unsigned b[2]) {
    asm volatile("mma.sync.aligned.m16n8k16.row.col.f32.f16.f16.f32 "
                 "{%0,%1,%2,%3}, {%4,%5,%6,%7}, {%8,%9}, {%0,%1,%2,%3};"
                 : "+f"(c[0]), "+f"(c[1]), "+f"(c[2]), "+f"(c[3])
                 : "r"(a[0]), "r"(a[1]), "r"(a[2]), "r"(a[3]), "r"(b[0]), "r"(b[1]));
}

// ================= fp16 msgs GEMM (pure cp.async, depth-2 pipeline) + attn_raw epilogue ======
// smem: A 3 slots x 10240 @0 ; W 3 slots x 10240 @30720. row stride 40 halfs (80B).
#define GSMEM_TOT 61440

__global__ __launch_bounds__(256, 2) void gemm_msgs_fused(int dummy) {
    extern __shared__ __align__(16) unsigned char smem[];
    uint32_t sbase;
    asm("{ .reg .u64 t; cvta.to.shared.u64 t, %1; cvt.u32.u64 %0, t; }" : "=r"(sbase) : "l"(smem));

    int tid  = threadIdx.x;
    int lane = tid & 31, wid = tid >> 5;
    int warp_m = wid & 3;
    int warp_n = wid >> 2;
    int  colBase = blockIdx.x * 128;
    long rowBase = (long)blockIdx.y * 128;

    float c[2][8][4];
#pragma unroll
    for (int i = 0; i < 2; i++)
#pragma unroll
        for (int j = 0; j < 8; j++)
#pragma unroll
            for (int k = 0; k < 4; k++) c[i][j][k] = 0.0f;

    unsigned aRow  = (lane & 15);
    unsigned aKoff = (lane >> 4) * 8;
    unsigned bRow  = (lane & 7) + ((lane >> 4) & 1) * 8;
    unsigned bKoff = ((lane >> 3) & 1) * 8;

    auto prefAW = [&](int kb, int slot) {
        unsigned aB = sbase + (unsigned)slot * 10240u;
        unsigned wB = sbase + 30720u + (unsigned)slot * 10240u;
#pragma unroll
        for (int t = 0; t < 2; t++) {
            int cc = tid + t * 256;
            int row = cc >> 2, q = cc & 3;
            unsigned off = (unsigned)(row * 40 + q * 8) * 2;
            CP_ASYNC16(aB + off, &g_A16[(rowBase + row) * 256 + kb * 32 + q * 8]);
            CP_ASYNC16(wB + off, &g_Wh[(colBase + row) * 256 + kb * 32 + q * 8]);
        }
        CP_COMMIT();
    };
    auto compute = [&](int slot) {
        unsigned aB = sbase + (unsigned)slot * 10240u;
        unsigned wT = sbase + 30720u + (unsigned)slot * 10240u;
#pragma unroll
        for (int kstep = 0; kstep < 2; kstep++) {
            int k0 = kstep * 16;
            unsigned a[2][4];
#pragma unroll
            for (int mi = 0; mi < 2; mi++)
                ldsm4(a[mi], aB + ((warp_m * 32 + mi * 16 + aRow) * 40 + k0 + aKoff) * 2);
            unsigned b[8][2];
#pragma unroll
            for (int pr = 0; pr < 4; pr++) {
                unsigned r[4];
                ldsm4(r, wT + ((warp_n * 64 + pr * 16 + bRow) * 40 + k0 + bKoff) * 2);
                b[pr * 2][0] = r[0]; b[pr * 2][1] = r[1];
                b[pr * 2 + 1][0] = r[2]; b[pr * 2 + 1][1] = r[3];
            }
#pragma unroll
            for (int mi = 0; mi < 2; mi++)
#pragma unroll
                for (int ni = 0; ni < 8; ni++)
                    mma16816(c[mi][ni], a[mi], b[ni]);
        }
    };

    // depth-2 pipeline over 3 slots, one sync per kb
    prefAW(0, 0);
    prefAW(1, 1);
    for (int kb = 0; kb < 8; kb++) {
        if (kb == 7) { CP_WAIT0(); } else { CP_WAIT1(); }   // slot kb complete
        __syncthreads();
        if (kb + 2 < 8) prefAW(kb + 2, (kb + 2) % 3);       // overwrites slot(kb-1): all reads done
        compute(kb % 3);
    }
    __syncthreads();

    // ---- epilogue 1: attn_raw partial dots (atomic) ----
    int b0 = (int)(rowBase / 200);
    int b1 = (int)((rowBase + 127) / 200);
    float* qpf = (float*)smem;
#pragma unroll
    for (int j = 0; j < 3; j++) {
        int idx = tid + j * 256;
        int s = idx >> 8, r = idx & 255;
        int bs = r >> 7, cc = r & 127;
        int bb = bs ? b1 : b0;
        qpf[idx] = g_qproj[(long)s * B_ * E_ + (long)bb * E_ + colBase + cc];
    }
    __syncthreads();

#pragma unroll
    for (int mi = 0; mi < 2; mi++) {
#pragma unroll
        for (int half = 0; half < 2; half++) {
            long grow = rowBase + warp_m * 32 + mi * 16 + (lane >> 2) + half * 8;
            int bs = (grow >= (long)(b0 + 1) * 200) ? 1 : 0;
            float p0 = 0.f, p1 = 0.f, p2 = 0.f;
#pragma unroll
            for (int ni = 0; ni < 8; ni++) {
                int cA = warp_n * 64 + ni * 8 + (lane & 3) * 2;
                float v0 = c[mi][ni][half * 2], v1 = c[mi][ni][half * 2 + 1];
                p0 = fmaf(v0, qpf[bs * 128 + cA],       fmaf(v1, qpf[bs * 128 + cA + 1],       p0));
                p1 = fmaf(v0, qpf[256 + bs * 128 + cA], fmaf(v1, qpf[256 + bs * 128 + cA + 1], p1));
                p2 = fmaf(v0, qpf[512 + bs * 128 + cA], fmaf(v1, qpf[512 + bs * 128 + cA + 1], p2));
            }
            p0 += __shfl_xor_sync(0xffffffffu, p0, 1); p0 += __shfl_xor_sync(0xffffffffu, p0, 2);
            p1 += __shfl_xor_sync(0xffffffffu, p1, 1); p1 += __shfl_xor_sync(0xffffffffu, p1, 2);
            p2 += __shfl_xor_sync(0xffffffffu, p2, 1); p2 += __shfl_xor_sync(0xffffffffu, p2, 2);
            if ((lane & 3) == 0) {
                atomicAdd(&g_attnraw[0 * B_ * N_ + grow], p0);
                atomicAdd(&g_attnraw[1 * B_ * N_ + grow], p1);
                atomicAdd(&g_attnraw[2 * B_ * N_ + grow], p2);
            }
        }
    }

    // ---- epilogue 2: store msgs (fp16) ----
    int g = lane >> 2, tc = lane & 3;
#pragma unroll
    for (int mi = 0; mi < 2; mi++) {
#pragma unroll
        for (int ni = 0; ni < 8; ni++) {
            long row = rowBase + warp_m * 32 + mi * 16 + g;
            int  col = colBase + warp_n * 64 + ni * 8 + tc * 2;
            __half2 h01(__float2half_rn(c[mi][ni][0]), __float2half_rn(c[mi][ni][1]));
            __half2 h23(__float2half_rn(c[mi][ni][2]), __float2half_rn(c[mi][ni][3]));
            *(__half2*)&g_msgs[row * E_ + col]       = h01;
            *(__half2*)&g_msgs[(row + 8) * E_ + col] = h23;
        }
    }
}

// ================= fp16 h-GEMM: g_h[s] = feats16[s] @ (sph+spl)[s]^T + sp_b =================
#define HG_SMEM 92160    // A: 3 x 10240 @0 ; W: 3 x (hi 10240 + lo 10240) @30720

__global__ __launch_bounds__(256, 2) void hgemm_kernel(const float* __restrict__ sp_b) {
    extern __shared__ __align__(16) unsigned char smem[];
    uint32_t sbase;
    asm("{ .reg .u64 t; cvta.to.shared.u64 t, %1; cvt.u32.u64 %0, t; }" : "=r"(sbase) : "l"(smem));

    int tid  = threadIdx.x;
    int lane = tid & 31, wid = tid >> 5;
    int warp_m = wid & 3;
    int warp_n = wid >> 2;
    int colBase = blockIdx.x * 128;
    int rowBase = blockIdx.y * 128;
    int s = blockIdx.z;

    const __half* Aa = g_feats16 + (long)s * B_ * SIXE;
    const __half* Wh = g_sph + (long)s * E_ * SIXE;
    const __half* Wl = g_spl + (long)s * E_ * SIXE;

    float c[2][8][4];
#pragma unroll
    for (int i = 0; i < 2; i++)
#pragma unroll
        for (int j = 0; j < 8; j++)
#pragma unroll
            for (int k = 0; k < 4; k++) c[i][j][k] = 0.0f;

    unsigned aRow  = (lane & 15);
    unsigned aKoff = (lane >> 4) * 8;
    unsigned bRow  = (lane & 7) + ((lane >> 4) & 1) * 8;
    unsigned bKoff = ((lane >> 3) & 1) * 8;

    auto pref = [&](int kb, int slot) {
        unsigned aB = sbase + (unsigned)slot * 10240u;
        unsigned wB = sbase + 30720u + (unsigned)slot * 20480u;
#pragma unroll
        for (int t = 0; t < 2; t++) {
            int cc = tid + t * 256;
            int row = cc >> 2, q = cc & 3;
            unsigned off = (unsigned)(row * 40 + q * 8) * 2;
            CP_ASYNC16(aB + off,          Aa + (long)(rowBase + row) * SIXE + kb * 32 + q * 8);
            CP_ASYNC16(wB + off,          Wh + (long)(colBase + row) * SIXE + kb * 32 + q * 8);
            CP_ASYNC16(wB + 10240u + off, Wl + (long)(colBase + row) * SIXE + kb * 32 + q * 8);
        }
        CP_COMMIT();
    };
    auto comp = [&](int slot) {
        unsigned aB = sbase + (unsigned)slot * 10240u;
        unsigned wB = sbase + 30720u + (unsigned)slot * 20480u;
#pragma unroll
        for (int kstep = 0; kstep < 2; kstep++) {
            int k0 = kstep * 16;
            unsigned a[2][4];
#pragma unroll
            for (int mi = 0; mi < 2; mi++)
                ldsm4(a[mi], aB + ((warp_m * 32 + mi * 16 + aRow) * 40 + k0 + aKoff) * 2);
#pragma unroll
            for (int v = 0; v < 2; v++) {
                unsigned wT = wB + (unsigned)v * 10240u;
                unsigned b[8][2];
#pragma unroll
                for (int pr = 0; pr < 4; pr++) {
                    unsigned r[4];
                    ldsm4(r, wT + ((warp_n * 64 + pr * 16 + bRow) * 40 + k0 + bKoff) * 2);
                    b[pr * 2][0] = r[0]; b[pr * 2][1] = r[1];
                    b[pr * 2 + 1][0] = r[2]; b[pr * 2 + 1][1] = r[3];
                }
#pragma unroll
                for (int mi = 0; mi < 2; mi++)
#pragma unroll
                    for (int ni = 0; ni < 8; ni++)
                        mma16816(c[mi][ni], a[mi], b[ni]);
            }
        }
    };

    // depth-2 pipeline, one sync per kb
    pref(0, 0);
    pref(1, 1);
    for (int kb = 0; kb < 48; kb++) {
        if (kb == 47) { CP_WAIT0(); } else { CP_WAIT1(); }
        __syncthreads();
        if (kb + 2 < 48) pref(kb + 2, (kb + 2) % 3);
        comp(kb % 3);
    }

    // epilogue: bias + store fp32
    int g = lane >> 2, tc = lane & 3;
#pragma unroll
    for (int mi = 0; mi < 2; mi++) {
#pragma unroll
        for (int ni = 0; ni < 8; ni++) {
            int row = rowBase + warp_m * 32 + mi * 16 + g;
            int col = colBase + warp_n * 64 + ni * 8 + tc * 2;
            float bb0 = sp_b[s * E_ + col], bb1 = sp_b[s * E_ + col + 1];
            long base = ((long)s * B_ + row) * E_ + col;
            g_h[base]            = c[mi][ni][0] + bb0;
            g_h[base + 1]        = c[mi][ni][1] + bb1;
            g_h[base + 8 * E_]     = c[mi][ni][2] + bb0;
            g_h[base + 8 * E_ + 1] = c[mi][ni][3] + bb1;
        }
    }
}

// ---------------- tiled SGEMM 64x64 (small fp32 GEMMs) ----------------
#define SBK 32
__global__ __launch_bounds__(256) void sgemm64_k(
    const float* __restrict__ A, const float* __restrict__ Bm, float* __restrict__ C,
    const float* __restrict__ bias, int M, int K,
    long sAz, long sBz, long sCz, long sbz) {
    A  += (long)blockIdx.z * sAz;
    Bm += (long)blockIdx.z * sBz;
    C  += (long)blockIdx.z * sCz;
    if (bias) bias += (long)blockIdx.z * sbz;

    __shared__ float As[SBK][68];
    __shared__ float Bs[SBK][64];
    int tid = threadIdx.x;
    int tx = tid & 15, ty = tid >> 4;
    int rowBase = blockIdx.x * 64;
    int colBase = blockIdx.y * 64;
    float acc[4][4];
#pragma unroll
    for (int i = 0; i < 4; i++)
#pragma unroll
        for (int j = 0; j < 4; j++) acc[i][j] = 0.0f;

    int nK = K / SBK;
    for (int kb = 0; kb < nK; kb++) {
        int kBase = kb * SBK;
#pragma unroll
        for (int it = 0; it < 2; it++) {
            int f4 = tid + it * 256;
            int row = f4 >> 3, k4 = f4 & 7;
            float4 v = *(const float4*)&A[(long)(rowBase + row) * K + kBase + k4 * 4];
            As[k4 * 4 + 0][row] = v.x;
            As[k4 * 4 + 1][row] = v.y;
            As[k4 * 4 + 2][row] = v.z;
            As[k4 * 4 + 3][row] = v.w;
        }
#pragma unroll
        for (int it = 0; it < 2; it++) {
            int f4 = tid + it * 256;
            int kr = f4 >> 4, c4 = f4 & 15;
            float4 v = *(const float4*)&Bm[(long)(kBase + kr) * E_ + colBase + c4 * 4];
            *(float4*)&Bs[kr][c4 * 4] = v;
        }
        __syncthreads();
#pragma unroll
        for (int k = 0; k < SBK; k++) {
            float a[4], bb[4];
#pragma unroll
            for (int i = 0; i < 4; i++) a[i] = As[k][ty * 4 + i];
#pragma unroll
            for (int j = 0; j < 4; j++) bb[j] = Bs[k][tx * 4 + j];
#pragma unroll
            for (int i = 0; i < 4; i++)
#pragma unroll
                for (int j = 0; j < 4; j++) acc[i][j] = fmaf(a[i], bb[j], acc[i][j]);
        }
        __syncthreads();
    }
#pragma unroll
    for (int i = 0; i < 4; i++) {
        long r = rowBase + ty * 4 + i;
#pragma unroll
        for (int j = 0; j < 4; j++) {
            int cc = colBase + tx * 4 + j;
            float v = acc[i][j];
            if (bias) v += bias[cc];
            C[r * E_ + cc] = v;
        }
    }
}

// ---------------- pooling ----------------
__global__ __launch_bounds__(256) void pool_kernel(const float* __restrict__ e_emb) {
    int b = blockIdx.x;
    int tid = threadIdx.x;

    __shared__ float4 s_scal[N_];
    __shared__ float4 s_ma[N_];
    __shared__ float4 s_pa[N_];
    __shared__ float  s_raw[3][N_];
    __shared__ float  s_red[256];

    for (int i = tid; i < N_; i += 256) {
        float4 sc = g_scal4[b * N_ + i];
        s_scal[i] = sc;
        s_ma[i] = make_float4(sc.x * sc.y, sc.x * sc.z, sc.x * sc.w,
                              sc.x > 0.0f ? 0.0f : 10000.0f);
    }
    __syncthreads();

    int anyv = g_anyvalid[b];

    if (tid < N_) {
        float4 sc = s_scal[tid];
        const float inv16 = 0.0625f;
#pragma unroll
        for (int s = 0; s < 3; s++) {
            float p = g_attnraw[s * B_ * N_ + b * N_ + tid];
            float r;
            if (!anyv)            r = 0.0f;
            else if (sc.x > 0.0f) r = p * ((s == 0) ? sc.y : (s == 1) ? sc.z : sc.w) * inv16;
            else                  r = -10000.0f;
            s_raw[s][tid] = r;
        }
    }
    __syncthreads();

    for (int s = 0; s < 3; s++) {
        float v = (tid < N_) ? s_raw[s][tid] : -INFINITY;
        s_red[tid] = v; __syncthreads();
        for (int off = 128; off; off >>= 1) {
            if (tid < off) s_red[tid] = fmaxf(s_red[tid], s_red[tid + off]);
            __syncthreads();
        }
        float mx = s_red[0]; __syncthreads();
        float p = (tid < N_) ? expf(v - mx) : 0.0f;
        s_red[tid] = p; __syncthreads();
        for (int off = 128; off; off >>= 1) {
            if (tid < off) s_red[tid] += s_red[tid + off];
            __syncthreads();
        }
        float inv = 1.0f / s_red[0]; __syncthreads();
        if (tid < N_) s_raw[s][tid] = p * inv;
        __syncthreads();
    }

    if (tid < N_) {
        float4 sc = s_scal[tid];
        s_pa[tid] = make_float4(s_raw[0][tid] * sc.y, s_raw[1][tid] * sc.z,
                                s_raw[2][tid] * sc.w, 0.0f);
    }
    __syncthreads();

    int e = tid;
    float mean[3] = {0.f, 0.f, 0.f};
    float sq[3]   = {0.f, 0.f, 0.f};
    float at[3]   = {0.f, 0.f, 0.f};
    float mx[3]   = {-INFINITY, -INFINITY, -INFINITY};
    float mn[3]   = { INFINITY,  INFINITY,  INFINITY};
    const __half* mp = g_msgs + (long)b * N_ * E_ + e;
    for (int n = 0; n < N_; n++) {
        float m = __half2float(mp[(long)n * E_]);
        float4 ma = s_ma[n];
        float4 pa = s_pa[n];
        float off = ma.w;
        {
            float vm = ma.x * m;
            mean[0] += vm;
            at[0] = fmaf(pa.x, m, at[0]);
            mx[0] = fmaxf(mx[0], vm);
            mn[0] = fminf(mn[0], vm + off);
            sq[0] += fminf(vm * vm, 100.0f);
        }
        {
            float vm = ma.y * m;
            mean[1] += vm;
            at[1] = fmaf(pa.y, m, at[1]);
            mx[1] = fmaxf(mx[1], vm);
            mn[1] = fminf(mn[1], vm + off);
            sq[1] += fminf(vm * vm, 100.0f);
        }
        {
            float vm = ma.z * m;
            mean[2] += vm;
            at[2] = fmaf(pa.z, m, at[2]);
            mx[2] = fmaxf(mx[2], vm);
            mn[2] = fminf(mn[2], vm + off);
            sq[2] += fminf(vm * vm, 100.0f);
        }
    }
    float inv_nv = 1.0f / g_nvalid[b];
    __half ee = __float2half_rn(e_emb[(long)b * E_ + e]);
#pragma unroll
    for (int s = 0; s < 3; s++) {
        long fb = ((long)s * B_ + b) * SIXE;
        float mv = mean[s] * inv_nv;
        float stdv = sqrtf(fmaxf(sq[s] * inv_nv - mv * mv, 1e-6f));
        float mnv = fminf(fmaxf(mn[s], -10000.0f), 10000.0f);
        g_feats16[fb +        e] = __float2half_rn(mv);
        g_feats16[fb +  256 + e] = __float2half_rn(mx[s]);
        g_feats16[fb +  512 + e] = __float2half_rn(mnv);
        g_feats16[fb +  768 + e] = __float2half_rn(stdv);
        g_feats16[fb + 1024 + e] = __float2half_rn(at[s]);
        g_feats16[fb + 1280 + e] = ee;
    }
}

// ---------------- layernorm + exact gelu ----------------
__global__ __launch_bounds__(256) void ln_gelu_kernel(const float* __restrict__ ln_g,
                                                      const float* __restrict__ ln_b) {
    int sb = blockIdx.x;
    int s = sb >> 10;
    int e = threadIdx.x;
    __shared__ float s_red[256];
    float x = g_h[(long)sb * E_ + e];
    s_red[e] = x; __syncthreads();
    for (int off = 128; off; off >>= 1) { if (e < off) s_red[e] += s_red[e + off]; __syncthreads(); }
    float mu = s_red[0] * (1.0f / 256.0f); __syncthreads();
    float d = x - mu;
    s_red[e] = d * d; __syncthreads();
    for (int off = 128; off; off >>= 1) { if (e < off) s_red[e] += s_red[e + off]; __syncthreads(); }
    float var = s_red[0] * (1.0f / 256.0f);
    float y = d * rsqrtf(var + 1e-5f) * ln_g[s * E_ + e] + ln_b[s * E_ + e];
    float g = 0.5f * y * (1.0f + erff(y * 0.70710678118654752f));
    g_scales[(long)sb * E_ + e] = g;
}

// ---------------- logits + softmax(3) + combine + final layernorm ----------------
__global__ __launch_bounds__(256) void final_kernel(const float* __restrict__ csl_w,
                                                    const float* __restrict__ csl_b,
                                                    const float* __restrict__ on_g,
                                                    const float* __restrict__ on_b,
                                                    float* __restrict__ out) {
    int b = blockIdx.x;
    int e = threadIdx.x;
    __shared__ float s_red[256];
    __shared__ float s_logit[3];
    float sqv = g_sq[(long)b * E_ + e];
    for (int s = 0; s < 3; s++) {
        s_red[e] = sqv * csl_w[s * E_ + e]; __syncthreads();
        for (int off = 128; off; off >>= 1) { if (e < off) s_red[e] += s_red[e + off]; __syncthreads(); }
        if (e == 0) s_logit[s] = s_red[0] + csl_b[s];
        __syncthreads();
    }
    float l0 = s_logit[0], l1 = s_logit[1], l2 = s_logit[2];
    float mm = fmaxf(l0, fmaxf(l1, l2));
    float w0 = expf(l0 - mm), w1 = expf(l1 - mm), w2 = expf(l2 - mm);
    float inv = 1.0f / (w0 + w1 + w2);
    w0 *= inv; w1 *= inv; w2 *= inv;
    float x = w0 * g_scales[((long)0 * B_ + b) * E_ + e]
            + w1 * g_scales[((long)1 * B_ + b) * E_ + e]
            + w2 * g_scales[((long)2 * B_ + b) * E_ + e];
    s_red[e] = x; __syncthreads();
    for (int off = 128; off; off >>= 1) { if (e < off) s_red[e] += s_red[e + off]; __syncthreads(); }
    float mu = s_red[0] * (1.0f / 256.0f); __syncthreads();
    float d = x - mu;
    s_red[e] = d * d; __syncthreads();
    for (int off = 128; off; off >>= 1) { if (e < off) s_red[e] += s_red[e + off]; __syncthreads(); }
    float var = s_red[0] * (1.0f / 256.0f);
    out[(long)b * E_ + e] = d * rsqrtf(var + 1e-5f) * on_g[e] + on_b[e];
}

// ---------------- host launcher ----------------
static float* symf(const void* symbol) {
    void* p = nullptr;
    cudaGetSymbolAddress(&p, symbol);
    return (float*)p;
}

extern "C" void kernel_launch(void* const* d_in, const int* in_sizes, int n_in,
                              void* d_out, int out_size) {
    const float* e_emb    = (const float*)d_in[0];
    const float* nb_rel   = (const float*)d_in[1];
    const float* delta_t  = (const float*)d_in[2];
    const float* r_emb    = (const float*)d_in[3];
    const void*  hist_mask=               d_in[4];
    const float* rel_w    = (const float*)d_in[5];
    const float* lt1      = (const float*)d_in[6];
    const float* lt2      = (const float*)d_in[7];
    const float* sharp    = (const float*)d_in[8];
    const float* lg       = (const float*)d_in[9];
    const float* attn_w   = (const float*)d_in[10];
    const float* sp_w     = (const float*)d_in[11];
    const float* sp_b     = (const float*)d_in[12];
    const float* ln_g     = (const float*)d_in[13];
    const float* ln_b     = (const float*)d_in[14];
    const float* csq_w    = (const float*)d_in[15];
    const float* csq_b    = (const float*)d_in[16];
    const float* csl_w    = (const float*)d_in[17];
    const float* csl_b    = (const float*)d_in[18];
    const float* on_g     = (const float*)d_in[19];
    const float* on_b     = (const float*)d_in[20];
    float* out = (float*)d_out;

    float* p_relwT  = symf(g_relwT);
    float* p_attnwT = symf(g_attnwT);
    float* p_csqwT  = symf(g_csqwT);
    float* p_qkey   = symf(g_qkey);
    float* p_qproj  = symf(g_qproj);
    float* p_sq     = symf(g_sq);

    cudaFuncSetAttribute(gemm_msgs_fused, cudaFuncAttributeMaxDynamicSharedMemorySize, GSMEM_TOT);
    cudaFuncSetAttribute(hgemm_kernel, cudaFuncAttributeMaxDynamicSharedMemorySize, HG_SMEM);

    dim3 tb(32, 8);
    wconv_kernel<<<64, 256>>>(rel_w);                                    // W + attnraw zero
    aconv_kernel<<<51200, 256>>>((const float4*)nb_rel);                 // nb_rel -> fp16
    transpose_kernel<<<dim3(8, 8, 1), tb>>>(rel_w,  p_relwT,  E_, R_);
    transpose_kernel<<<dim3(8, 8, 3), tb>>>(attn_w, p_attnwT, E_, E_);
    sgemm64_k<<<dim3(16, 4, 1), 256>>>(r_emb, p_relwT, p_qkey, nullptr,
                                       B_, R_, 0, 0, 0, 0);
    sgemm64_k<<<dim3(16, 4, 3), 256>>>(p_qkey, p_attnwT, p_qproj, nullptr,
                                       B_, E_, 0, (long)E_ * E_, (long)B_ * E_, 0);
    gemm_msgs_fused<<<dim3(2, 1600), 256, GSMEM_TOT>>>(0);

    detect_mask_kernel<<<1, 256>>>((const unsigned char*)hist_mask, B_ * N_);
    prep_kernel<<<B_, 256>>>(hist_mask, delta_t, lt1, lt2, sharp, lg);
    transpose_kernel<<<dim3(8, 8, 1), tb>>>(csq_w, p_csqwT, E_, R_);
    sgemm64_k<<<dim3(16, 4, 1), 256>>>(r_emb, p_csqwT, p_sq, csq_b,
                                       B_, R_, 0, 0, 0, 0);
    spsplit_kernel<<<1152, 256>>>(sp_w);

    pool_kernel<<<B_, 256>>>(e_emb);
    hgemm_kernel<<<dim3(2, 8, 3), 256, HG_SMEM>>>(sp_b);
    ln_gelu_kernel<<<3 * B_, 256>>>(ln_g, ln_b);
    final_kernel<<<B_, 256>>>(csl_w, csl_b, on_g, on_b, out);
}

// round 17
// speedup vs baseline: 1.0716x; 1.0716x over previous
#include <cuda_runtime.h>
#include <cuda_bf16.h>
#include <cuda_fp16.h>
#include <math.h>
#include <stdint.h>

#define B_   1024
#define N_   200
#define E_   256
#define R_   256
#define SIXE 1536

// ---------------- device scratch (static, no allocation) ----------------
__device__ __align__(16) __half g_msgs  [B_ * N_ * E_];   // 105 MB
__device__ __align__(16) __half g_Wh[E_ * R_];            // rel_w fp16 [E,R]
__device__ float  g_attnraw[3 * B_ * N_];
__device__ __align__(16) __half g_feats16[3 * B_ * SIXE];
__device__ __align__(16) __half g_sph[3 * E_ * SIXE];     // sp_w fp16
__device__ float  g_relwT [R_ * E_];
__device__ float  g_attnwT[3 * E_ * E_];
__device__ float  g_csqwT [R_ * E_];
__device__ float  g_qkey  [B_ * E_];
__device__ float  g_qproj [3 * B_ * E_];
__device__ float  g_sq    [B_ * E_];
__device__ float  g_h     [3 * B_ * E_];
__device__ float  g_scales[3 * B_ * E_];
__device__ float4 g_scal4 [B_ * N_];       // (maskf, a0, a1, a2)
__device__ float  g_nvalid[B_];
__device__ int    g_anyvalid[B_];
__device__ int    g_mask_mode;

// ---------------- mask dtype detection ----------------
__global__ void detect_mask_kernel(const unsigned char* __restrict__ raw, int nElems) {
    __shared__ int f1, f23;
    if (threadIdx.x == 0) { f1 = 0; f23 = 0; }
    __syncthreads();
    int lf1 = 0, lf23 = 0;
    for (int i = threadIdx.x; i < nElems; i += blockDim.x) {
        unsigned char v = raw[i];
        if (v) { int m = i & 3; if (m == 1) lf1 = 1; else if (m >= 2) lf23 = 1; }
    }
    if (lf1)  atomicOr(&f1, 1);
    if (lf23) atomicOr(&f23, 1);
    __syncthreads();
    if (threadIdx.x == 0) g_mask_mode = f1 ? 1 : (f23 ? 2 : 0);
}

// ---------------- per-(b,n) scalar precompute ----------------
__global__ void prep_kernel(const void* __restrict__ maskp,
                            const float* __restrict__ delta_t,
                            const float* __restrict__ p_lt1, const float* __restrict__ p_lt2,
                            const float* __restrict__ p_sharp, const float* __restrict__ p_lg) {
    int b = blockIdx.x;
    int n = threadIdx.x;
    __shared__ int s_cnt[256];
    int mode = g_mask_mode;
    float tau1  = expf(*p_lt1);
    float tau2  = expf(*p_lt2) + tau1;
    float sharp = fminf(fmaxf(*p_sharp, 0.1f), 5.0f);
    float gamma = expf(*p_lg);
    int valid = 0;
    if (n < N_) {
        int idx = b * N_ + n;
        if      (mode == 0) valid = ((const int*)maskp)[idx] != 0;
        else if (mode == 1) valid = ((const unsigned char*)maskp)[idx] != 0;
        else                valid = ((const float*)maskp)[idx] != 0.0f;
        float dt    = delta_t[idx];
        float decay = expf(-gamma * fmaxf(dt, 0.0f));
        float wf = 1.0f / (1.0f + expf( sharp * (dt - tau1)));
        float wc = 1.0f / (1.0f + expf(-sharp * (dt - tau2)));
        float wm = fmaxf(1.0f - wf - wc, 0.0f);
        g_scal4[idx] = make_float4(valid ? 1.0f : 0.0f, decay * wf, decay * wm, decay * wc);
    }
    s_cnt[threadIdx.x] = valid;
    __syncthreads();
    for (int off = 128; off > 0; off >>= 1) {
        if (threadIdx.x < off) s_cnt[threadIdx.x] += s_cnt[threadIdx.x + off];
        __syncthreads();
    }
    if (threadIdx.x == 0) {
        g_nvalid[b]   = fmaxf((float)s_cnt[0], 1.0f);
        g_anyvalid[b] = (s_cnt[0] > 0) ? 1 : 0;
    }
}

// ---------------- W convert + attnraw zero ----------------
__global__ void wconv_kernel(const float* __restrict__ rel_w) {
    int idx = blockIdx.x * 256 + threadIdx.x;        // 16384 float4s
    float4 v = ((const float4*)rel_w)[idx];
    __half2 hA(__float2half_rn(v.x), __float2half_rn(v.y));
    __half2 hB(__float2half_rn(v.z), __float2half_rn(v.w));
    *(uint2*)&g_Wh[idx * 4] = make_uint2(*(uint32_t*)&hA, *(uint32_t*)&hB);
    float4* ar = (float4*)g_attnraw;
    for (int i = idx; i < 153600; i += 16384)
        ar[i] = make_float4(0.f, 0.f, 0.f, 0.f);
}

// ---------------- sp_w convert: [3,E,6E] fp32 -> fp16 ----------------
__global__ void spconv_kernel(const float* __restrict__ sp_w) {
    int idx = blockIdx.x * 256 + threadIdx.x;        // 294912 float4s
    float4 v = ((const float4*)sp_w)[idx];
    __half2 hA(__float2half_rn(v.x), __float2half_rn(v.y));
    __half2 hB(__float2half_rn(v.z), __float2half_rn(v.w));
    *(uint2*)&g_sph[idx * 4] = make_uint2(*(uint32_t*)&hA, *(uint32_t*)&hB);
}

// ---------------- generic transpose ----------------
__global__ void transpose_kernel(const float* __restrict__ in, float* __restrict__ out,
                                 int rows, int cols) {
    long zoff = (long)blockIdx.z * rows * cols;
    in  += zoff;
    out += zoff;
    __shared__ float tile[32][33];
    int c0 = blockIdx.x * 32, r0 = blockIdx.y * 32;
    int c = c0 + threadIdx.x;
    for (int i = threadIdx.y; i < 32; i += 8) {
        int r = r0 + i;
        if (r < rows && c < cols) tile[i][threadIdx.x] = in[(long)r * cols + c];
    }
    __syncthreads();
    int rr = r0 + threadIdx.x;
    for (int i = threadIdx.y; i < 32; i += 8) {
        int cc = c0 + i;
        if (cc < cols && rr < rows) out[(long)cc * rows + rr] = tile[threadIdx.x][i];
    }
}

// ================= common MMA helpers =================
#define CP_ASYNC16(sa, ga) asm volatile("cp.async.cg.shared.global [%0], [%1], 16;\n" :: "r"(sa), "l"(ga))
#define CP_COMMIT()        asm volatile("cp.async.commit_group;\n" ::)
#define CP_WAIT0()         asm volatile("cp.async.wait_group 0;\n" ::)

__device__ __forceinline__ void ldsm4(unsigned r[4], unsigned addr) {
    asm volatile("ldmatrix.sync.aligned.m8n8.x4.shared.b16 {%0,%1,%2,%3}, [%4];"
                 : "=r"(r[0]), "=r"(r[1]), "=r"(r[2]), "=r"(r[3]) : "r"(addr));
}
__device__ __forceinline__ void mma16816(float c[4], const unsigned a[4], const unsigned b[2]) {
    asm volatile("mma.sync.aligned.m16n8k16.row.col.f32.f16.f16.f32 "
                 "{%0,%1,%2,%3}, {%4,%5,%6,%7}, {%8,%9}, {%0,%1,%2,%3};"
                 : "+f"(c[0]), "+f"(c[1]), "+f"(c[2]), "+f"(c[3])
                 : "r"(a[0]), "r"(a[1]), "r"(a[2]), "r"(a[3]), "r"(b[0]), "r"(b[1]));
}

// ================= fused fp16 msgs GEMM (round-14 proven) + attn_raw epilogue ======
// smem: A 3 slots x 10240 @0 ; W 3 slots x 10240 @30720. row stride 40 halfs (80B).
#define GSMEM_TOT 61440

__global__ __launch_bounds__(256, 2) void gemm_msgs_fused(const float* __restrict__ nbrel) {
    extern __shared__ __align__(16) unsigned char smem[];
    uint32_t sbase;
    asm("{ .reg .u64 t; cvta.to.shared.u64 t, %1; cvt.u32.u64 %0, t; }" : "=r"(sbase) : "l"(smem));

    int tid  = threadIdx.x;
    int lane = tid & 31, wid = tid >> 5;
    int warp_m = wid & 3;
    int warp_n = wid >> 2;
    int  colBase = blockIdx.x * 128;
    long rowBase = (long)blockIdx.y * 128;

    float c[2][8][4];
#pragma unroll
    for (int i = 0; i < 2; i++)
#pragma unroll
        for (int j = 0; j < 8; j++)
#pragma unroll
            for (int k = 0; k < 4; k++) c[i][j][k] = 0.0f;

    unsigned aRow  = (lane & 15);
    unsigned aKoff = (lane >> 4) * 8;
    unsigned bRow  = (lane & 7) + ((lane >> 4) & 1) * 8;
    unsigned bKoff = ((lane >> 3) & 1) * 8;

    float4 areg[4];
    auto loadA = [&](int kb) {
#pragma unroll
        for (int i = 0; i < 4; i++) {
            int f4 = tid + i * 256;
            int row = f4 >> 3, k4 = f4 & 7;
            areg[i] = *(const float4*)&nbrel[(rowBase + row) * 256 + kb * 32 + k4 * 4];
        }
    };
    auto storeA = [&](int slot) {
        unsigned base = (unsigned)slot * 10240u;
#pragma unroll
        for (int i = 0; i < 4; i++) {
            int f4 = tid + i * 256;
            int row = f4 >> 3, k4 = f4 & 7;
            unsigned off = base + (unsigned)(row * 40 + k4 * 4) * 2;
            float4 v = areg[i];
            __half2 hA(__float2half_rn(v.x), __float2half_rn(v.y));
            __half2 hB(__float2half_rn(v.z), __float2half_rn(v.w));
            *(uint2*)(smem + off) = make_uint2(*(uint32_t*)&hA, *(uint32_t*)&hB);
        }
    };
    auto prefW = [&](int kb, int slot) {
        unsigned wb = sbase + 30720u + (unsigned)slot * 10240u;
#pragma unroll
        for (int t = 0; t < 2; t++) {
            int cc = tid + t * 256;
            int row = cc >> 2, q = cc & 3;
            unsigned off = (unsigned)(row * 40 + q * 8) * 2;
            CP_ASYNC16(wb + off, &g_Wh[(colBase + row) * 256 + kb * 32 + q * 8]);
        }
        CP_COMMIT();
    };
    auto compute = [&](int slot) {
        unsigned aB = sbase + (unsigned)slot * 10240u;
        unsigned wT = sbase + 30720u + (unsigned)slot * 10240u;
#pragma unroll
        for (int kstep = 0; kstep < 2; kstep++) {
            int k0 = kstep * 16;
            unsigned a[2][4];
#pragma unroll
            for (int mi = 0; mi < 2; mi++)
                ldsm4(a[mi], aB + ((warp_m * 32 + mi * 16 + aRow) * 40 + k0 + aKoff) * 2);
            unsigned b[8][2];
#pragma unroll
            for (int pr = 0; pr < 4; pr++) {
                unsigned r[4];
                ldsm4(r, wT + ((warp_n * 64 + pr * 16 + bRow) * 40 + k0 + bKoff) * 2);
                b[pr * 2][0] = r[0]; b[pr * 2][1] = r[1];
                b[pr * 2 + 1][0] = r[2]; b[pr * 2 + 1][1] = r[3];
            }
#pragma unroll
            for (int mi = 0; mi < 2; mi++)
#pragma unroll
                for (int ni = 0; ni < 8; ni++)
                    mma16816(c[mi][ni], a[mi], b[ni]);
        }
    };

    // prologue: slot 0 ready
    loadA(0);
    prefW(0, 0);
    storeA(0);
    CP_WAIT0();
    __syncthreads();

    for (int kb = 0; kb < 8; kb++) {
        int slot = kb % 3;
        if (kb < 7) {
            loadA(kb + 1);
            prefW(kb + 1, (kb + 1) % 3);
        }
        compute(slot);
        if (kb < 7) {
            storeA((kb + 1) % 3);
            CP_WAIT0();
            __syncthreads();
        }
    }
    __syncthreads();

    // ---- epilogue 1: attn_raw partial dots (atomic) ----
    int b0 = (int)(rowBase / 200);
    int b1 = (int)((rowBase + 127) / 200);
    float* qpf = (float*)smem;
#pragma unroll
    for (int j = 0; j < 3; j++) {
        int idx = tid + j * 256;
        int s = idx >> 8, r = idx & 255;
        int bs = r >> 7, cc = r & 127;
        int bb = bs ? b1 : b0;
        qpf[idx] = g_qproj[(long)s * B_ * E_ + (long)bb * E_ + colBase + cc];
    }
    __syncthreads();

#pragma unroll
    for (int mi = 0; mi < 2; mi++) {
#pragma unroll
        for (int half = 0; half < 2; half++) {
            long grow = rowBase + warp_m * 32 + mi * 16 + (lane >> 2) + half * 8;
            int bs = (grow >= (long)(b0 + 1) * 200) ? 1 : 0;
            float p0 = 0.f, p1 = 0.f, p2 = 0.f;
#pragma unroll
            for (int ni = 0; ni < 8; ni++) {
                int cA = warp_n * 64 + ni * 8 + (lane & 3) * 2;
                float v0 = c[mi][ni][half * 2], v1 = c[mi][ni][half * 2 + 1];
                p0 = fmaf(v0, qpf[bs * 128 + cA],       fmaf(v1, qpf[bs * 128 + cA + 1],       p0));
                p1 = fmaf(v0, qpf[256 + bs * 128 + cA], fmaf(v1, qpf[256 + bs * 128 + cA + 1], p1));
                p2 = fmaf(v0, qpf[512 + bs * 128 + cA], fmaf(v1, qpf[512 + bs * 128 + cA + 1], p2));
            }
            p0 += __shfl_xor_sync(0xffffffffu, p0, 1); p0 += __shfl_xor_sync(0xffffffffu, p0, 2);
            p1 += __shfl_xor_sync(0xffffffffu, p1, 1); p1 += __shfl_xor_sync(0xffffffffu, p1, 2);
            p2 += __shfl_xor_sync(0xffffffffu, p2, 1); p2 += __shfl_xor_sync(0xffffffffu, p2, 2);
            if ((lane & 3) == 0) {
                atomicAdd(&g_attnraw[0 * B_ * N_ + grow], p0);
                atomicAdd(&g_attnraw[1 * B_ * N_ + grow], p1);
                atomicAdd(&g_attnraw[2 * B_ * N_ + grow], p2);
            }
        }
    }

    // ---- epilogue 2: store msgs (fp16) ----
    int g = lane >> 2, tc = lane & 3;
#pragma unroll
    for (int mi = 0; mi < 2; mi++) {
#pragma unroll
        for (int ni = 0; ni < 8; ni++) {
            long row = rowBase + warp_m * 32 + mi * 16 + g;
            int  col = colBase + warp_n * 64 + ni * 8 + tc * 2;
            __half2 h01(__float2half_rn(c[mi][ni][0]), __float2half_rn(c[mi][ni][1]));
            __half2 h23(__float2half_rn(c[mi][ni][2]), __float2half_rn(c[mi][ni][3]));
            *(__half2*)&g_msgs[row * E_ + col]       = h01;
            *(__half2*)&g_msgs[(row + 8) * E_ + col] = h23;
        }
    }
}

// ================= fp16 h-GEMM: g_h[s] = feats16[s] @ sph[s]^T + sp_b ==============
// 128 rows x 64 cols per CTA, grid (4, 8, 3) = 96 blocks. Static smem 46 KB.
__global__ __launch_bounds__(256, 2) void hgemm_kernel(const float* __restrict__ sp_b) {
    __shared__ __align__(16) unsigned char smem[46080];   // A 3x10240 @0 ; W 3x5120 @30720
    uint32_t sbase;
    asm("{ .reg .u64 t; cvta.to.shared.u64 t, %1; cvt.u32.u64 %0, t; }" : "=r"(sbase) : "l"(smem));

    int tid  = threadIdx.x;
    int lane = tid & 31, wid = tid >> 5;
    int warp_m = wid & 3;          // 4 warps x 32 rows
    int warp_n = wid >> 2;         // 2 warps x 32 cols
    int colBase = blockIdx.x * 64;
    int rowBase = blockIdx.y * 128;
    int s = blockIdx.z;

    const __half* Aa = g_feats16 + (long)s * B_ * SIXE;
    const __half* Wp = g_sph + (long)s * E_ * SIXE;

    float c[2][4][4];
#pragma unroll
    for (int i = 0; i < 2; i++)
#pragma unroll
        for (int j = 0; j < 4; j++)
#pragma unroll
            for (int k = 0; k < 4; k++) c[i][j][k] = 0.0f;

    unsigned aRow  = (lane & 15);
    unsigned aKoff = (lane >> 4) * 8;
    unsigned bRow  = (lane & 7) + ((lane >> 4) & 1) * 8;
    unsigned bKoff = ((lane >> 3) & 1) * 8;

    auto pref = [&](int kb, int slot) {
        unsigned aB = sbase + (unsigned)slot * 10240u;
        unsigned wB = sbase + 30720u + (unsigned)slot * 5120u;
#pragma unroll
        for (int t = 0; t < 2; t++) {    // A: 512 chunks
            int cc = tid + t * 256;
            int row = cc >> 2, q = cc & 3;
            unsigned off = (unsigned)(row * 40 + q * 8) * 2;
            CP_ASYNC16(aB + off, Aa + (long)(rowBase + row) * SIXE + kb * 32 + q * 8);
        }
        {                                 // W: 256 chunks
            int row = tid >> 2, q = tid & 3;
            unsigned off = (unsigned)(row * 40 + q * 8) * 2;
            CP_ASYNC16(wB + off, Wp + (long)(colBase + row) * SIXE + kb * 32 + q * 8);
        }
        CP_COMMIT();
    };
    auto comp = [&](int slot) {
        unsigned aB = sbase + (unsigned)slot * 10240u;
        unsigned wT = sbase + 30720u + (unsigned)slot * 5120u;
#pragma unroll
        for (int kstep = 0; kstep < 2; kstep++) {
            int k0 = kstep * 16;
            unsigned a[2][4];
#pragma unroll
            for (int mi = 0; mi < 2; mi++)
                ldsm4(a[mi], aB + ((warp_m * 32 + mi * 16 + aRow) * 40 + k0 + aKoff) * 2);
            unsigned b[4][2];
#pragma unroll
            for (int pr = 0; pr < 2; pr++) {
                unsigned r[4];
                ldsm4(r, wT + ((warp_n * 32 + pr * 16 + bRow) * 40 + k0 + bKoff) * 2);
                b[pr * 2][0] = r[0]; b[pr * 2][1] = r[1];
                b[pr * 2 + 1][0] = r[2]; b[pr * 2 + 1][1] = r[3];
            }
#pragma unroll
            for (int mi = 0; mi < 2; mi++)
#pragma unroll
                for (int ni = 0; ni < 4; ni++)
                    mma16816(c[mi][ni], a[mi], b[ni]);
        }
    };

    pref(0, 0);
    CP_WAIT0();
    __syncthreads();

    for (int kb = 0; kb < 48; kb++) {
        int slot = kb % 3;
        if (kb < 47) pref(kb + 1, (kb + 1) % 3);
        comp(slot);
        if (kb < 47) {
            CP_WAIT0();
            __syncthreads();
        }
    }

    // epilogue: bias + store fp32
    int g = lane >> 2, tc = lane & 3;
#pragma unroll
    for (int mi = 0; mi < 2; mi++) {
#pragma unroll
        for (int ni = 0; ni < 4; ni++) {
            int row = rowBase + warp_m * 32 + mi * 16 + g;
            int col = colBase + warp_n * 32 + ni * 8 + tc * 2;
            float bb0 = sp_b[s * E_ + col], bb1 = sp_b[s * E_ + col + 1];
            long base = ((long)s * B_ + row) * E_ + col;
            g_h[base]            = c[mi][ni][0] + bb0;
            g_h[base + 1]        = c[mi][ni][1] + bb1;
            g_h[base + 8 * E_]     = c[mi][ni][2] + bb0;
            g_h[base + 8 * E_ + 1] = c[mi][ni][3] + bb1;
        }
    }
}

// ---------------- tiled SGEMM 64x64 (small fp32 GEMMs) ----------------
#define SBK 32
__global__ __launch_bounds__(256) void sgemm64_k(
    const float* __restrict__ A, const float* __restrict__ Bm, float* __restrict__ C,
    const float* __restrict__ bias, int M, int K,
    long sAz, long sBz, long sCz, long sbz) {
    A  += (long)blockIdx.z * sAz;
    Bm += (long)blockIdx.z * sBz;
    C  += (long)blockIdx.z * sCz;
    if (bias) bias += (long)blockIdx.z * sbz;

    __shared__ float As[SBK][68];
    __shared__ float Bs[SBK][64];
    int tid = threadIdx.x;
    int tx = tid & 15, ty = tid >> 4;
    int rowBase = blockIdx.x * 64;
    int colBase = blockIdx.y * 64;
    float acc[4][4];
#pragma unroll
    for (int i = 0; i < 4; i++)
#pragma unroll
        for (int j = 0; j < 4; j++) acc[i][j] = 0.0f;

    int nK = K / SBK;
    for (int kb = 0; kb < nK; kb++) {
        int kBase = kb * SBK;
#pragma unroll
        for (int it = 0; it < 2; it++) {
            int f4 = tid + it * 256;
            int row = f4 >> 3, k4 = f4 & 7;
            float4 v = *(const float4*)&A[(long)(rowBase + row) * K + kBase + k4 * 4];
            As[k4 * 4 + 0][row] = v.x;
            As[k4 * 4 + 1][row] = v.y;
            As[k4 * 4 + 2][row] = v.z;
            As[k4 * 4 + 3][row] = v.w;
        }
#pragma unroll
        for (int it = 0; it < 2; it++) {
            int f4 = tid + it * 256;
            int kr = f4 >> 4, c4 = f4 & 15;
            float4 v = *(const float4*)&Bm[(long)(kBase + kr) * E_ + colBase + c4 * 4];
            *(float4*)&Bs[kr][c4 * 4] = v;
        }
        __syncthreads();
#pragma unroll
        for (int k = 0; k < SBK; k++) {
            float a[4], bb[4];
#pragma unroll
            for (int i = 0; i < 4; i++) a[i] = As[k][ty * 4 + i];
#pragma unroll
            for (int j = 0; j < 4; j++) bb[j] = Bs[k][tx * 4 + j];
#pragma unroll
            for (int i = 0; i < 4; i++)
#pragma unroll
                for (int j = 0; j < 4; j++) acc[i][j] = fmaf(a[i], bb[j], acc[i][j]);
        }
        __syncthreads();
    }
#pragma unroll
    for (int i = 0; i < 4; i++) {
        long r = rowBase + ty * 4 + i;
#pragma unroll
        for (int j = 0; j < 4; j++) {
            int cc = colBase + tx * 4 + j;
            float v = acc[i][j];
            if (bias) v += bias[cc];
            C[r * E_ + cc] = v;
        }
    }
}

// ---------------- pooling ----------------
__global__ __launch_bounds__(256) void pool_kernel(const float* __restrict__ e_emb) {
    int b = blockIdx.x;
    int tid = threadIdx.x;

    __shared__ float4 s_scal[N_];
    __shared__ float4 s_ma[N_];
    __shared__ float4 s_pa[N_];
    __shared__ float  s_raw[3][N_];
    __shared__ float  s_red[256];

    for (int i = tid; i < N_; i += 256) {
        float4 sc = g_scal4[b * N_ + i];
        s_scal[i] = sc;
        s_ma[i] = make_float4(sc.x * sc.y, sc.x * sc.z, sc.x * sc.w,
                              sc.x > 0.0f ? 0.0f : 10000.0f);
    }
    __syncthreads();

    int anyv = g_anyvalid[b];

    if (tid < N_) {
        float4 sc = s_scal[tid];
        const float inv16 = 0.0625f;
#pragma unroll
        for (int s = 0; s < 3; s++) {
            float p = g_attnraw[s * B_ * N_ + b * N_ + tid];
            float r;
            if (!anyv)            r = 0.0f;
            else if (sc.x > 0.0f) r = p * ((s == 0) ? sc.y : (s == 1) ? sc.z : sc.w) * inv16;
            else                  r = -10000.0f;
            s_raw[s][tid] = r;
        }
    }
    __syncthreads();

    for (int s = 0; s < 3; s++) {
        float v = (tid < N_) ? s_raw[s][tid] : -INFINITY;
        s_red[tid] = v; __syncthreads();
        for (int off = 128; off; off >>= 1) {
            if (tid < off) s_red[tid] = fmaxf(s_red[tid], s_red[tid + off]);
            __syncthreads();
        }
        float mx = s_red[0]; __syncthreads();
        float p = (tid < N_) ? expf(v - mx) : 0.0f;
        s_red[tid] = p; __syncthreads();
        for (int off = 128; off; off >>= 1) {
            if (tid < off) s_red[tid] += s_red[tid + off];
            __syncthreads();
        }
        float inv = 1.0f / s_red[0]; __syncthreads();
        if (tid < N_) s_raw[s][tid] = p * inv;
        __syncthreads();
    }

    if (tid < N_) {
        float4 sc = s_scal[tid];
        s_pa[tid] = make_float4(s_raw[0][tid] * sc.y, s_raw[1][tid] * sc.z,
                                s_raw[2][tid] * sc.w, 0.0f);
    }
    __syncthreads();

    int e = tid;
    float mean[3] = {0.f, 0.f, 0.f};
    float sq[3]   = {0.f, 0.f, 0.f};
    float at[3]   = {0.f, 0.f, 0.f};
    float mx[3]   = {-INFINITY, -INFINITY, -INFINITY};
    float mn[3]   = { INFINITY,  INFINITY,  INFINITY};
    const __half* mp = g_msgs + (long)b * N_ * E_ + e;
    for (int n = 0; n < N_; n++) {
        float m = __half2float(mp[(long)n * E_]);
        float4 ma = s_ma[n];
        float4 pa = s_pa[n];
        float off = ma.w;
        {
            float vm = ma.x * m;
            mean[0] += vm;
            at[0] = fmaf(pa.x, m, at[0]);
            mx[0] = fmaxf(mx[0], vm);
            mn[0] = fminf(mn[0], vm + off);
            sq[0] += fminf(vm * vm, 100.0f);
        }
        {
            float vm = ma.y * m;
            mean[1] += vm;
            at[1] = fmaf(pa.y, m, at[1]);
            mx[1] = fmaxf(mx[1], vm);
            mn[1] = fminf(mn[1], vm + off);
            sq[1] += fminf(vm * vm, 100.0f);
        }
        {
            float vm = ma.z * m;
            mean[2] += vm;
            at[2] = fmaf(pa.z, m, at[2]);
            mx[2] = fmaxf(mx[2], vm);
            mn[2] = fminf(mn[2], vm + off);
            sq[2] += fminf(vm * vm, 100.0f);
        }
    }
    float inv_nv = 1.0f / g_nvalid[b];
    __half ee = __float2half_rn(e_emb[(long)b * E_ + e]);
#pragma unroll
    for (int s = 0; s < 3; s++) {
        long fb = ((long)s * B_ + b) * SIXE;
        float mv = mean[s] * inv_nv;
        float stdv = sqrtf(fmaxf(sq[s] * inv_nv - mv * mv, 1e-6f));
        float mnv = fminf(fmaxf(mn[s], -10000.0f), 10000.0f);
        g_feats16[fb +        e] = __float2half_rn(mv);
        g_feats16[fb +  256 + e] = __float2half_rn(mx[s]);
        g_feats16[fb +  512 + e] = __float2half_rn(mnv);
        g_feats16[fb +  768 + e] = __float2half_rn(stdv);
        g_feats16[fb + 1024 + e] = __float2half_rn(at[s]);
        g_feats16[fb + 1280 + e] = ee;
    }
}

// ---------------- layernorm + exact gelu ----------------
__global__ __launch_bounds__(256) void ln_gelu_kernel(const float* __restrict__ ln_g,
                                                      const float* __restrict__ ln_b) {
    int sb = blockIdx.x;
    int s = sb >> 10;
    int e = threadIdx.x;
    __shared__ float s_red[256];
    float x = g_h[(long)sb * E_ + e];
    s_red[e] = x; __syncthreads();
    for (int off = 128; off; off >>= 1) { if (e < off) s_red[e] += s_red[e + off]; __syncthreads(); }
    float mu = s_red[0] * (1.0f / 256.0f); __syncthreads();
    float d = x - mu;
    s_red[e] = d * d; __syncthreads();
    for (int off = 128; off; off >>= 1) { if (e < off) s_red[e] += s_red[e + off]; __syncthreads(); }
    float var = s_red[0] * (1.0f / 256.0f);
    float y = d * rsqrtf(var + 1e-5f) * ln_g[s * E_ + e] + ln_b[s * E_ + e];
    float g = 0.5f * y * (1.0f + erff(y * 0.70710678118654752f));
    g_scales[(long)sb * E_ + e] = g;
}

// ---------------- logits + softmax(3) + combine + final layernorm ----------------
__global__ __launch_bounds__(256) void final_kernel(const float* __restrict__ csl_w,
                                                    const float* __restrict__ csl_b,
                                                    const float* __restrict__ on_g,
                                                    const float* __restrict__ on_b,
                                                    float* __restrict__ out) {
    int b = blockIdx.x;
    int e = threadIdx.x;
    __shared__ float s_red[256];
    __shared__ float s_logit[3];
    float sqv = g_sq[(long)b * E_ + e];
    for (int s = 0; s < 3; s++) {
        s_red[e] = sqv * csl_w[s * E_ + e]; __syncthreads();
        for (int off = 128; off; off >>= 1) { if (e < off) s_red[e] += s_red[e + off]; __syncthreads(); }
        if (e == 0) s_logit[s] = s_red[0] + csl_b[s];
        __syncthreads();
    }
    float l0 = s_logit[0], l1 = s_logit[1], l2 = s_logit[2];
    float mm = fmaxf(l0, fmaxf(l1, l2));
    float w0 = expf(l0 - mm), w1 = expf(l1 - mm), w2 = expf(l2 - mm);
    float inv = 1.0f / (w0 + w1 + w2);
    w0 *= inv; w1 *= inv; w2 *= inv;
    float x = w0 * g_scales[((long)0 * B_ + b) * E_ + e]
            + w1 * g_scales[((long)1 * B_ + b) * E_ + e]
            + w2 * g_scales[((long)2 * B_ + b) * E_ + e];
    s_red[e] = x; __syncthreads();
    for (int off = 128; off; off >>= 1) { if (e < off) s_red[e] += s_red[e + off]; __syncthreads(); }
    float mu = s_red[0] * (1.0f / 256.0f); __syncthreads();
    float d = x - mu;
    s_red[e] = d * d; __syncthreads();
    for (int off = 128; off; off >>= 1) { if (e < off) s_red[e] += s_red[e + off]; __syncthreads(); }
    float var = s_red[0] * (1.0f / 256.0f);
    out[(long)b * E_ + e] = d * rsqrtf(var + 1e-5f) * on_g[e] + on_b[e];
}

// ---------------- host launcher ----------------
static float* symf(const void* symbol) {
    void* p = nullptr;
    cudaGetSymbolAddress(&p, symbol);
    return (float*)p;
}

extern "C" void kernel_launch(void* const* d_in, const int* in_sizes, int n_in,
                              void* d_out, int out_size) {
    const float* e_emb    = (const float*)d_in[0];
    const float* nb_rel   = (const float*)d_in[1];
    const float* delta_t  = (const float*)d_in[2];
    const float* r_emb    = (const float*)d_in[3];
    const void*  hist_mask=               d_in[4];
    const float* rel_w    = (const float*)d_in[5];
    const float* lt1      = (const float*)d_in[6];
    const float* lt2      = (const float*)d_in[7];
    const float* sharp    = (const float*)d_in[8];
    const float* lg       = (const float*)d_in[9];
    const float* attn_w   = (const float*)d_in[10];
    const float* sp_w     = (const float*)d_in[11];
    const float* sp_b     = (const float*)d_in[12];
    const float* ln_g     = (const float*)d_in[13];
    const float* ln_b     = (const float*)d_in[14];
    const float* csq_w    = (const float*)d_in[15];
    const float* csq_b    = (const float*)d_in[16];
    const float* csl_w    = (const float*)d_in[17];
    const float* csl_b    = (const float*)d_in[18];
    const float* on_g     = (const float*)d_in[19];
    const float* on_b     = (const float*)d_in[20];
    float* out = (float*)d_out;

    float* p_relwT  = symf(g_relwT);
    float* p_attnwT = symf(g_attnwT);
    float* p_csqwT  = symf(g_csqwT);
    float* p_qkey   = symf(g_qkey);
    float* p_qproj  = symf(g_qproj);
    float* p_sq     = symf(g_sq);

    cudaFuncSetAttribute(gemm_msgs_fused, cudaFuncAttributeMaxDynamicSharedMemorySize, GSMEM_TOT);

    dim3 tb(32, 8);
    wconv_kernel<<<64, 256>>>(rel_w);                                    // W + attnraw zero
    transpose_kernel<<<dim3(8, 8, 1), tb>>>(rel_w,  p_relwT,  E_, R_);
    transpose_kernel<<<dim3(8, 8, 3), tb>>>(attn_w, p_attnwT, E_, E_);
    sgemm64_k<<<dim3(16, 4, 1), 256>>>(r_emb, p_relwT, p_qkey, nullptr,
                                       B_, R_, 0, 0, 0, 0);
    sgemm64_k<<<dim3(16, 4, 3), 256>>>(p_qkey, p_attnwT, p_qproj, nullptr,
                                       B_, E_, 0, (long)E_ * E_, (long)B_ * E_, 0);
    gemm_msgs_fused<<<dim3(2, 1600), 256, GSMEM_TOT>>>(nb_rel);

    detect_mask_kernel<<<1, 256>>>((const unsigned char*)hist_mask, B_ * N_);
    prep_kernel<<<B_, 256>>>(hist_mask, delta_t, lt1, lt2, sharp, lg);
    transpose_kernel<<<dim3(8, 8, 1), tb>>>(csq_w, p_csqwT, E_, R_);
    sgemm64_k<<<dim3(16, 4, 1), 256>>>(r_emb, p_csqwT, p_sq, csq_b,
                                       B_, R_, 0, 0, 0, 0);
    spconv_kernel<<<1152, 256>>>(sp_w);

    pool_kernel<<<B_, 256>>>(e_emb);
    hgemm_kernel<<<dim3(4, 8, 3), 256>>>(sp_b);
    ln_gelu_kernel<<<3 * B_, 256>>>(ln_g, ln_b);
    final_kernel<<<B_, 256>>>(csl_w, csl_b, on_g, on_b, out);
}